// round 2
// baseline (speedup 1.0000x reference)
#include <cuda_runtime.h>
#include <cstdint>

#define N_NODES   50000
#define IN_FEAT   128
#define OUT_FEAT  128
#define NB        16
#define SI        8
#define SO        8
#define W_PER_REL (NB * SI * SO)   // 1024
#define E_MAX     500000
#define MAXR      256

// Scratch (static device globals — allocation-free per harness rules)
__device__ int4 g_edges[E_MAX];     // (src, dst, etype, norm_bits) sorted by etype
__device__ int  g_hist[MAXR];
__device__ int  g_cursor[MAXR];

// ---------------------------------------------------------------------------
// Vectorized global float4 reduction (sm_90+)
// ---------------------------------------------------------------------------
__device__ __forceinline__ void red_add_v4(float* addr, float4 v) {
    asm volatile("red.global.add.v4.f32 [%0], {%1, %2, %3, %4};"
                 :: "l"(addr), "f"(v.x), "f"(v.y), "f"(v.z), "f"(v.w)
                 : "memory");
}

// ---------------------------------------------------------------------------
// Sort phase: counting sort of edges by etype
// ---------------------------------------------------------------------------
__global__ void zero_hist_kernel() {
    g_hist[threadIdx.x] = 0;
}

__global__ void hist_kernel(const int* __restrict__ et, int n) {
    __shared__ int sh[MAXR];
    sh[threadIdx.x] = 0;
    __syncthreads();
    for (int i = blockIdx.x * blockDim.x + threadIdx.x; i < n;
         i += gridDim.x * blockDim.x)
        atomicAdd(&sh[et[i]], 1);
    __syncthreads();
    int v = sh[threadIdx.x];
    if (v) atomicAdd(&g_hist[threadIdx.x], v);
}

__global__ void scan_kernel() {
    __shared__ int sh[MAXR];
    int t = threadIdx.x;
    int v = g_hist[t];
    sh[t] = v;
    __syncthreads();
    for (int off = 1; off < MAXR; off <<= 1) {
        int x = (t >= off) ? sh[t - off] : 0;
        __syncthreads();
        sh[t] += x;
        __syncthreads();
    }
    g_cursor[t] = sh[t] - v;   // exclusive prefix
}

__global__ void scatter_kernel(const int* __restrict__ src,
                               const int* __restrict__ dst,
                               const int* __restrict__ et,
                               const float* __restrict__ norm, int n) {
    int i = blockIdx.x * blockDim.x + threadIdx.x;
    if (i >= n) return;
    int t = et[i];
    int pos = atomicAdd(&g_cursor[t], 1);
    int d = dst[i];
    int4 ed;
    ed.x = src[i];
    ed.y = d;
    ed.z = t;
    ed.w = __float_as_int(__ldg(norm + d));
    g_edges[pos] = ed;
}

// ---------------------------------------------------------------------------
// Kernel A: d_out = h @ loop_weight  (register-tiled, 64 rows x 128 cols/block)
// 256 threads: thread -> 8 rows x 4 cols (32 accumulators)
// ---------------------------------------------------------------------------
#define GM_ROWS 64
__global__ __launch_bounds__(256) void loop_gemm_kernel(
        const float* __restrict__ h,
        const float* __restrict__ lw,
        float* __restrict__ out) {
    __shared__ float4 xs[GM_ROWS][32];   // 32 KB tile of h
    int r0 = blockIdx.x * GM_ROWS;
    int tid = threadIdx.x;

    const float4* h4 = reinterpret_cast<const float4*>(h);
    for (int idx = tid; idx < GM_ROWS * 32; idx += 256) {
        int r = idx >> 5, c = idx & 31;
        int gr = r0 + r;
        xs[r][c] = (gr < N_NODES) ? __ldg(&h4[(size_t)gr * 32 + c])
                                  : make_float4(0.f, 0.f, 0.f, 0.f);
    }
    __syncthreads();

    int cx = tid & 31;          // float4 column index (cols 4cx..4cx+3)
    int rg = (tid >> 5) * 8;    // row base within tile

    float4 acc[8];
#pragma unroll
    for (int r = 0; r < 8; r++) acc[r] = make_float4(0.f, 0.f, 0.f, 0.f);

    const float4* lw4 = reinterpret_cast<const float4*>(lw);
    const float* xrow = reinterpret_cast<const float*>(&xs[rg][0]);

#pragma unroll 4
    for (int k = 0; k < IN_FEAT; k++) {
        float4 w = __ldg(&lw4[(size_t)k * 32 + cx]);
#pragma unroll
        for (int r = 0; r < 8; r++) {
            float x = xrow[r * IN_FEAT + k];   // warp-uniform broadcast LDS
            acc[r].x = fmaf(x, w.x, acc[r].x);
            acc[r].y = fmaf(x, w.y, acc[r].y);
            acc[r].z = fmaf(x, w.z, acc[r].z);
            acc[r].w = fmaf(x, w.w, acc[r].w);
        }
    }

    float4* out4 = reinterpret_cast<float4*>(out);
#pragma unroll
    for (int r = 0; r < 8; r++) {
        int gr = r0 + rg + r;
        if (gr < N_NODES) out4[(size_t)gr * 32 + cx] = acc[r];
    }
}

// ---------------------------------------------------------------------------
// Kernel B: one warp per (etype-sorted) edge.
//   lane l: basis block b = l>>1, output offset o0 = (l&1)*4
//   red.global.add.v4( out + dst*128 + 4l, msg * norm[dst] )
// Sorted order -> W[t] stays hot in L1 across consecutive warps.
// ---------------------------------------------------------------------------
__global__ __launch_bounds__(256) void edge_kernel(
        const float* __restrict__ h,
        const float* __restrict__ weight,
        float* __restrict__ out,
        int nedges) {
    int gw   = (blockIdx.x * blockDim.x + threadIdx.x) >> 5;
    int lane = threadIdx.x & 31;
    if (gw >= nedges) return;

    int4 ed = g_edges[gw];           // warp-uniform broadcast
    int s = ed.x, d = ed.y, t = ed.z;
    float nrm = __int_as_float(ed.w);

    int b  = lane >> 1;
    int o0 = (lane & 1) * 4;

    const float4* xp = reinterpret_cast<const float4*>(h + (size_t)s * IN_FEAT + b * SI);
    float4 xa = __ldg(xp);
    float4 xb = __ldg(xp + 1);
    float x[8] = {xa.x, xa.y, xa.z, xa.w, xb.x, xb.y, xb.z, xb.w};

    const float* wb = weight + (size_t)t * W_PER_REL + b * (SI * SO) + o0;

    float4 acc = make_float4(0.f, 0.f, 0.f, 0.f);
#pragma unroll
    for (int i = 0; i < SI; i++) {
        float4 w = __ldg(reinterpret_cast<const float4*>(wb + i * SO));
        acc.x = fmaf(x[i], w.x, acc.x);
        acc.y = fmaf(x[i], w.y, acc.y);
        acc.z = fmaf(x[i], w.z, acc.z);
        acc.w = fmaf(x[i], w.w, acc.w);
    }

    acc.x *= nrm; acc.y *= nrm; acc.z *= nrm; acc.w *= nrm;
    red_add_v4(out + (size_t)d * OUT_FEAT + lane * 4, acc);
}

// ---------------------------------------------------------------------------
// Kernel C: in-place ReLU (float4 vectorized)
// ---------------------------------------------------------------------------
__global__ void relu_kernel(float4* __restrict__ out, int n4) {
    int i = blockIdx.x * blockDim.x + threadIdx.x;
    if (i >= n4) return;
    float4 v = out[i];
    v.x = fmaxf(v.x, 0.f);
    v.y = fmaxf(v.y, 0.f);
    v.z = fmaxf(v.z, 0.f);
    v.w = fmaxf(v.w, 0.f);
    out[i] = v;
}

// ---------------------------------------------------------------------------
// Launch: sort (4 kernels) -> GEMM init -> edge scatter -> ReLU
// Inputs (metadata order): h, norm, weight, loop_weight, src, dst, etype
// ---------------------------------------------------------------------------
extern "C" void kernel_launch(void* const* d_in, const int* in_sizes, int n_in,
                              void* d_out, int out_size) {
    const float* h      = (const float*)d_in[0];
    const float* norm   = (const float*)d_in[1];
    const float* weight = (const float*)d_in[2];
    const float* lw     = (const float*)d_in[3];
    const int*   src    = (const int*)d_in[4];
    const int*   dst    = (const int*)d_in[5];
    const int*   etype  = (const int*)d_in[6];
    float* out = (float*)d_out;

    int nedges = in_sizes[4];
    if (nedges > E_MAX) nedges = E_MAX;

    // ---- sort edges by etype ----
    zero_hist_kernel<<<1, MAXR>>>();
    hist_kernel<<<232, MAXR>>>(etype, nedges);
    scan_kernel<<<1, MAXR>>>();
    scatter_kernel<<<(nedges + 255) / 256, 256>>>(src, dst, etype, norm, nedges);

    // ---- self-loop GEMM (initializes d_out) ----
    loop_gemm_kernel<<<(N_NODES + GM_ROWS - 1) / GM_ROWS, 256>>>(h, lw, out);

    // ---- per-edge messages, norm-scaled, vector red into d_out ----
    {
        int warps_per_block = 256 / 32;
        int blocks = (nedges + warps_per_block - 1) / warps_per_block;
        edge_kernel<<<blocks, 256>>>(h, weight, out, nedges);
    }

    // ---- ReLU ----
    {
        int n4 = N_NODES * OUT_FEAT / 4;
        relu_kernel<<<(n4 + 255) / 256, 256>>>((float4*)out, n4);
    }
}

// round 3
// speedup vs baseline: 2.7346x; 2.7346x over previous
#include <cuda_runtime.h>
#include <cstdint>

#define N_NODES   50000
#define IN_FEAT   128
#define OUT_FEAT  128
#define NB        16
#define SI        8
#define SO        8
#define W_PER_REL (NB * SI * SO)   // 1024
#define E_MAX     500000
#define MAXR      200
#define SORT_TPB  256
#define NBLK_MAX  ((E_MAX + SORT_TPB - 1) / SORT_TPB)   // 1954
#define EPW       8                 // edges per warp in edge kernel

// Scratch (static device globals — allocation-free per harness rules)
__device__ int4 g_edges[E_MAX];             // (src, dst, etype, norm_bits), etype-sorted
__device__ int  g_bh[MAXR * NBLK_MAX];      // per-(rel, block) counts -> base offsets
__device__ int  g_rel_total[MAXR];
__device__ int  g_rel_base[MAXR];

// ---------------------------------------------------------------------------
__device__ __forceinline__ void red_add_v4(float* addr, float4 v) {
    asm volatile("red.global.add.v4.f32 [%0], {%1, %2, %3, %4};"
                 :: "l"(addr), "f"(v.x), "f"(v.y), "f"(v.z), "f"(v.w)
                 : "memory");
}

// ---------------------------------------------------------------------------
// Sort pass 1: per-block histogram  (grid = nblk, 256 thr)
// ---------------------------------------------------------------------------
__global__ void k_hist(const int* __restrict__ et, int n, int nblk) {
    __shared__ int sh[MAXR];
    int tid = threadIdx.x, bid = blockIdx.x;
    if (tid < MAXR) sh[tid] = 0;
    __syncthreads();
    int e = bid * SORT_TPB + tid;
    if (e < n) atomicAdd(&sh[et[e]], 1);
    __syncthreads();
    if (tid < MAXR) g_bh[tid * nblk + bid] = sh[tid];
}

// Sort pass 2a: row sums  (grid = MAXR, 256 thr)
__global__ void k_rowsum(int nblk) {
    __shared__ int sh[SORT_TPB];
    int r = blockIdx.x, tid = threadIdx.x;
    int s = 0;
    for (int j = tid; j < nblk; j += SORT_TPB) s += g_bh[r * nblk + j];
    sh[tid] = s;
    __syncthreads();
    for (int off = SORT_TPB / 2; off > 0; off >>= 1) {
        if (tid < off) sh[tid] += sh[tid + off];
        __syncthreads();
    }
    if (tid == 0) g_rel_total[r] = sh[0];
}

// Sort pass 2b: exclusive scan over relations  (1 block, 256 thr)
__global__ void k_relscan() {
    __shared__ int sh[SORT_TPB];
    int t = threadIdx.x;
    int v = (t < MAXR) ? g_rel_total[t] : 0;
    sh[t] = v;
    __syncthreads();
    for (int off = 1; off < SORT_TPB; off <<= 1) {
        int x = (t >= off) ? sh[t - off] : 0;
        __syncthreads();
        sh[t] += x;
        __syncthreads();
    }
    if (t < MAXR) g_rel_base[t] = sh[t] - v;
}

// Sort pass 2c: per-relation exclusive scan over blocks, in place
// (grid = MAXR, 256 thr; chunked Hillis-Steele with running carry)
__global__ void k_rowscan(int nblk) {
    __shared__ int sh[SORT_TPB];
    int r = blockIdx.x, tid = threadIdx.x;
    int carry = g_rel_base[r];
    for (int base = 0; base < nblk; base += SORT_TPB) {
        int j = base + tid;
        int v = (j < nblk) ? g_bh[r * nblk + j] : 0;
        sh[tid] = v;
        __syncthreads();
        for (int off = 1; off < SORT_TPB; off <<= 1) {
            int x = (tid >= off) ? sh[tid - off] : 0;
            __syncthreads();
            sh[tid] += x;
            __syncthreads();
        }
        if (j < nblk) g_bh[r * nblk + j] = carry + sh[tid] - v;  // exclusive
        int chunk_total = sh[SORT_TPB - 1];
        __syncthreads();
        carry += chunk_total;
    }
}

// Sort pass 3: scatter with shared cursors (NO global atomics)
__global__ void k_scatter(const int* __restrict__ src,
                          const int* __restrict__ dst,
                          const int* __restrict__ et,
                          const float* __restrict__ norm,
                          int n, int nblk) {
    __shared__ int cur[MAXR];
    int tid = threadIdx.x, bid = blockIdx.x;
    if (tid < MAXR) cur[tid] = g_bh[tid * nblk + bid];
    __syncthreads();
    int e = bid * SORT_TPB + tid;
    if (e >= n) return;
    int t = et[e];
    int pos = atomicAdd(&cur[t], 1);
    int d = dst[e];
    int4 ed;
    ed.x = src[e];
    ed.y = d;
    ed.z = t;
    ed.w = __float_as_int(__ldg(norm + d));
    g_edges[pos] = ed;
}

// ---------------------------------------------------------------------------
// Kernel A: d_out = h @ loop_weight  (register-tiled, 64 rows x 128 cols/block)
// ---------------------------------------------------------------------------
#define GM_ROWS 64
__global__ __launch_bounds__(256) void loop_gemm_kernel(
        const float* __restrict__ h,
        const float* __restrict__ lw,
        float* __restrict__ out) {
    __shared__ float4 xs[GM_ROWS][32];
    int r0 = blockIdx.x * GM_ROWS;
    int tid = threadIdx.x;

    const float4* h4 = reinterpret_cast<const float4*>(h);
    for (int idx = tid; idx < GM_ROWS * 32; idx += 256) {
        int r = idx >> 5, c = idx & 31;
        int gr = r0 + r;
        xs[r][c] = (gr < N_NODES) ? __ldg(&h4[(size_t)gr * 32 + c])
                                  : make_float4(0.f, 0.f, 0.f, 0.f);
    }
    __syncthreads();

    int cx = tid & 31;
    int rg = (tid >> 5) * 8;

    float4 acc[8];
#pragma unroll
    for (int r = 0; r < 8; r++) acc[r] = make_float4(0.f, 0.f, 0.f, 0.f);

    const float4* lw4 = reinterpret_cast<const float4*>(lw);
    const float* xrow = reinterpret_cast<const float*>(&xs[rg][0]);

#pragma unroll 4
    for (int k = 0; k < IN_FEAT; k++) {
        float4 w = __ldg(&lw4[(size_t)k * 32 + cx]);
#pragma unroll
        for (int r = 0; r < 8; r++) {
            float x = xrow[r * IN_FEAT + k];
            acc[r].x = fmaf(x, w.x, acc[r].x);
            acc[r].y = fmaf(x, w.y, acc[r].y);
            acc[r].z = fmaf(x, w.z, acc[r].z);
            acc[r].w = fmaf(x, w.w, acc[r].w);
        }
    }

    float4* out4 = reinterpret_cast<float4*>(out);
#pragma unroll
    for (int r = 0; r < 8; r++) {
        int gr = r0 + rg + r;
        if (gr < N_NODES) out4[(size_t)gr * 32 + cx] = acc[r];
    }
}

// ---------------------------------------------------------------------------
// Kernel B: each warp processes EPW consecutive etype-sorted edges,
// caching the relation's W block in registers across edges.
//   lane l: basis block b = l>>1, output offset o0 = (l&1)*4
// ---------------------------------------------------------------------------
__global__ __launch_bounds__(256) void edge_kernel(
        const float* __restrict__ h,
        const float* __restrict__ weight,
        float* __restrict__ out,
        int nedges) {
    int gw   = (blockIdx.x * blockDim.x + threadIdx.x) >> 5;
    int lane = threadIdx.x & 31;
    int e0 = gw * EPW;
    if (e0 >= nedges) return;

    int b  = lane >> 1;
    int o0 = (lane & 1) * 4;

    int t_cur = -1;
    float4 w[SI];

    int e_end = e0 + EPW;
    if (e_end > nedges) e_end = nedges;

    for (int e = e0; e < e_end; e++) {
        int4 ed = g_edges[e];                 // warp-uniform broadcast load
        int s = ed.x, d = ed.y, t = ed.z;
        float nrm = __int_as_float(ed.w);

        if (t != t_cur) {                     // warp-uniform branch
            t_cur = t;
            const float* wb = weight + (size_t)t * W_PER_REL + b * (SI * SO) + o0;
#pragma unroll
            for (int i = 0; i < SI; i++)
                w[i] = __ldg(reinterpret_cast<const float4*>(wb + i * SO));
        }

        const float4* xp = reinterpret_cast<const float4*>(h + (size_t)s * IN_FEAT + b * SI);
        float4 xa = __ldg(xp);
        float4 xb = __ldg(xp + 1);
        float x[8] = {xa.x, xa.y, xa.z, xa.w, xb.x, xb.y, xb.z, xb.w};

        float4 acc = make_float4(0.f, 0.f, 0.f, 0.f);
#pragma unroll
        for (int i = 0; i < SI; i++) {
            acc.x = fmaf(x[i], w[i].x, acc.x);
            acc.y = fmaf(x[i], w[i].y, acc.y);
            acc.z = fmaf(x[i], w[i].z, acc.z);
            acc.w = fmaf(x[i], w[i].w, acc.w);
        }

        acc.x *= nrm; acc.y *= nrm; acc.z *= nrm; acc.w *= nrm;
        red_add_v4(out + (size_t)d * OUT_FEAT + lane * 4, acc);
    }
}

// ---------------------------------------------------------------------------
// Kernel C: in-place ReLU (float4 vectorized)
// ---------------------------------------------------------------------------
__global__ void relu_kernel(float4* __restrict__ out, int n4) {
    int i = blockIdx.x * blockDim.x + threadIdx.x;
    if (i >= n4) return;
    float4 v = out[i];
    v.x = fmaxf(v.x, 0.f);
    v.y = fmaxf(v.y, 0.f);
    v.z = fmaxf(v.z, 0.f);
    v.w = fmaxf(v.w, 0.f);
    out[i] = v;
}

// ---------------------------------------------------------------------------
// Launch: 5-kernel contention-free sort -> GEMM init -> edge scatter -> ReLU
// Inputs (metadata order): h, norm, weight, loop_weight, src, dst, etype
// ---------------------------------------------------------------------------
extern "C" void kernel_launch(void* const* d_in, const int* in_sizes, int n_in,
                              void* d_out, int out_size) {
    const float* h      = (const float*)d_in[0];
    const float* norm   = (const float*)d_in[1];
    const float* weight = (const float*)d_in[2];
    const float* lw     = (const float*)d_in[3];
    const int*   src    = (const int*)d_in[4];
    const int*   dst    = (const int*)d_in[5];
    const int*   etype  = (const int*)d_in[6];
    float* out = (float*)d_out;

    int nedges = in_sizes[4];
    if (nedges > E_MAX) nedges = E_MAX;
    int nblk = (nedges + SORT_TPB - 1) / SORT_TPB;

    // ---- contention-free counting sort by etype ----
    k_hist<<<nblk, SORT_TPB>>>(etype, nedges, nblk);
    k_rowsum<<<MAXR, SORT_TPB>>>(nblk);
    k_relscan<<<1, SORT_TPB>>>();
    k_rowscan<<<MAXR, SORT_TPB>>>(nblk);
    k_scatter<<<nblk, SORT_TPB>>>(src, dst, etype, norm, nedges, nblk);

    // ---- self-loop GEMM (initializes d_out) ----
    loop_gemm_kernel<<<(N_NODES + GM_ROWS - 1) / GM_ROWS, 256>>>(h, lw, out);

    // ---- per-edge messages (W cached in registers across EPW edges) ----
    {
        int nwarps = (nedges + EPW - 1) / EPW;
        int blocks = (nwarps + 7) / 8;       // 8 warps / block
        edge_kernel<<<blocks, 256>>>(h, weight, out, nedges);
    }

    // ---- ReLU ----
    {
        int n4 = N_NODES * OUT_FEAT / 4;
        relu_kernel<<<(n4 + 255) / 256, 256>>>((float4*)out, n4);
    }
}